// round 13
// baseline (speedup 1.0000x reference)
#include <cuda_runtime.h>
#include <cstdint>

#define G_    8
#define FG_   16
#define J_    8
#define W_    31
#define PAD1_ 15
#define L_    262144
#define KTILE_ 512
#define NTH_  256

// SMEM layout (32-bit words). yt ALIASES xs+ws (dead after main loop).
// xs shifted: xs[j][s] = x[kb + s - 16], s in [0,544); consumers read +1.
#define XS_PITCH 548
#define XS_ELEMS (J_ * XS_PITCH)         // 4384
#define WS_ELEMS (J_ * 4 * 32 * 4)       // 4096 words (uint4 slots)
#define YT_PITCH 516
#define YT_ELEMS (FG_ * YT_PITCH)        // 8256
#define SM_XS 0
#define SM_WS (SM_XS + XS_ELEMS)         // 4384
#define SM_YT 0
#define SMEM_WORDS (SM_WS + WS_ELEMS)    // 8480 words = 33920 B

// Pre-transformed weights: [g][slot] uint4 image, 32768 words = 128 KB.
__device__ uint32_t d_wt[G_ * WS_ELEMS];

__device__ __forceinline__ uint32_t cvt_tf32(float f) {
    uint32_t r;
    asm("cvt.rna.tf32.f32 %0, %1;" : "=r"(r) : "f"(f));
    return r;
}
__device__ __forceinline__ void cp16(uint32_t dst_smem, const void* src) {
    asm volatile("cp.async.cg.shared.global [%0], [%1], 16;"
                 :: "r"(dst_smem), "l"(src) : "memory");
}
#define CP_COMMIT() asm volatile("cp.async.commit_group;" ::: "memory")
#define CP_WAIT(N)  asm volatile("cp.async.wait_group " #N ";" ::: "memory")

__device__ __forceinline__ void mma_tf32(float d[4],
                                         uint32_t a0, uint32_t a1,
                                         uint32_t a2, uint32_t a3,
                                         uint32_t b0, uint32_t b1) {
    asm volatile(
        "mma.sync.aligned.m16n8k8.row.col.f32.tf32.tf32.f32 "
        "{%0,%1,%2,%3}, {%4,%5,%6,%7}, {%8,%9}, {%0,%1,%2,%3};"
        : "+f"(d[0]), "+f"(d[1]), "+f"(d[2]), "+f"(d[3])
        : "r"(a0), "r"(a1), "r"(a2), "r"(a3), "r"(b0), "r"(b1));
}

// Prep: transform params [g][f][j][w] -> d_wt uint4-slot image (rna tf32).
__global__ void prep_w(const float* __restrict__ params) {
    int idx = blockIdx.x * blockDim.x + threadIdx.x;
    if (idx >= G_ * WS_ELEMS) return;
    int c    = idx & 3;
    int ln   = (idx >> 2) & 31;
    int w0g  = (idx >> 7) & 3;
    int j    = (idx >> 9) & 7;
    int g    = idx >> 12;
    int f    = ((c >> 1) << 3) + (ln >> 2);
    int w    = w0g * 8 + (ln & 3) + ((c & 1) << 2);
    float v  = (w < W_) ? params[((g * FG_ + f) * J_ + j) * W_ + w] : 0.f;
    d_wt[idx] = cvt_tf32(v);
}

// CTA: one group g, 512 consecutive k, 16 filters. Warp: 64 k x 16 f.
// A[m,kk] = xs[j][m + w0 + kk] (Toeplitz alias; X[22] register window).
// Staging: 2 cp.async groups {ws+x0..x3}, {x4..x7}; 2 waits total.
__global__ void __launch_bounds__(NTH_, 4)
conv_mma(const float* __restrict__ x,
         const float* __restrict__ params,
         const int* __restrict__ rel,
         float* __restrict__ out)
{
    extern __shared__ uint32_t sm[];
    const uint32_t smb = (uint32_t)__cvta_generic_to_shared(sm);
    const int tid  = threadIdx.x;
    const int wid  = tid >> 5;
    const int lane = tid & 31;
    const int gid  = lane >> 2;
    const int tig  = lane & 3;
    const int g    = blockIdx.y;
    const int tile = blockIdx.x;
    const int kb   = tile * KTILE_;
    const int last = L_ / KTILE_ - 1;
    const bool interior = (tile != 0) && (tile != last);

    int rows[J_];
#pragma unroll
    for (int j = 0; j < J_; ++j) rows[j] = __ldg(rel + g * J_ + j);

    // ---- group A: weights image + x windows j=0..3 ----
    {
        const uint32_t* src = d_wt + g * WS_ELEMS;
        for (int e = tid; e < WS_ELEMS / 4; e += NTH_)
            cp16(smb + (SM_WS + e * 4) * 4, src + e * 4);
    }
    if (interior) {
#pragma unroll
        for (int j = 0; j < 4; ++j) {
            const char* xp = (const char*)(x + rows[j] * L_ + kb - 16);
            uint32_t xd = smb + (SM_XS + j * XS_PITCH) * 4;
            for (int q = tid; q < 136; q += NTH_)
                cp16(xd + 16 * q, xp + 16 * q);
        }
        CP_COMMIT();
        // ---- group B: x windows j=4..7 ----
#pragma unroll
        for (int j = 4; j < J_; ++j) {
            const char* xp = (const char*)(x + rows[j] * L_ + kb - 16);
            uint32_t xd = smb + (SM_XS + j * XS_PITCH) * 4;
            for (int q = tid; q < 136; q += NTH_)
                cp16(xd + 16 * q, xp + 16 * q);
        }
        CP_COMMIT();
    } else {
        CP_COMMIT();
        // edge tiles: clamped scalar path (pollutes only overwritten outputs)
#pragma unroll 1
        for (int j = 0; j < J_; ++j) {
            const float* xr = x + rows[j] * L_;
            for (int s = tid; s < 544; s += NTH_) {
                int gi = kb + s - 16;
                gi = max(0, min(L_ - 1, gi));
                sm[SM_XS + j * XS_PITCH + s] = __float_as_uint(__ldg(xr + gi));
            }
        }
        CP_COMMIT();   // keep group count = 2 on all paths
    }

    const int warpk = wid * 64;

    float acc[4][2][4];
#pragma unroll
    for (int mi = 0; mi < 4; ++mi)
#pragma unroll
        for (int nh = 0; nh < 2; ++nh)
#pragma unroll
            for (int q = 0; q < 4; ++q) acc[mi][nh][q] = 0.f;

    CP_WAIT(1);        // group A resident
    __syncthreads();

#pragma unroll
    for (int j = 0; j < J_; ++j) {
        if (j == 4) {  // group B resident
            CP_WAIT(0);
            __syncthreads();
        }

        const uint32_t* xj = sm + SM_XS + j * XS_PITCH + 1 + warpk + gid + tig;
        const uint4* wj = (const uint4*)(sm + SM_WS + j * 512) + lane;

        uint32_t X[22];
#pragma unroll
        for (int i = 0; i < 22; ++i) X[i] = xj[4 * i];

        uint4 B = wj[0];
#pragma unroll
        for (int w0g = 0; w0g < 4; ++w0g) {
            uint4 Bn = wj[(w0g < 3 ? w0g + 1 : 3) * 32];
#pragma unroll
            for (int mi = 0; mi < 4; ++mi) {
                const int i0 = 4 * mi + 2 * w0g;
                mma_tf32(acc[mi][0], X[i0], X[i0 + 2], X[i0 + 1], X[i0 + 3], B.x, B.y);
                mma_tf32(acc[mi][1], X[i0], X[i0 + 2], X[i0 + 1], X[i0 + 3], B.z, B.w);
            }
            B = Bn;
        }
    }

    __syncthreads();   // xs/ws dead; yt aliases them

    // ---- warp-local epilogue: this warp owns k in [warpk, warpk+64) ----
    float* yt = (float*)(sm + SM_YT);
#pragma unroll
    for (int mi = 0; mi < 4; ++mi) {
        const int k0 = warpk + mi * 16 + gid;
#pragma unroll
        for (int nh = 0; nh < 2; ++nh) {
            const int f0 = nh * 8 + 2 * tig;
            yt[f0 * YT_PITCH + k0]           = acc[mi][nh][0];
            yt[(f0 + 1) * YT_PITCH + k0]     = acc[mi][nh][1];
            yt[f0 * YT_PITCH + k0 + 8]       = acc[mi][nh][2];
            yt[(f0 + 1) * YT_PITCH + k0 + 8] = acc[mi][nh][3];
        }
    }
    __syncwarp();

    // per-warp coalesced store of its own k-slice: 16 f x 16 float4
#pragma unroll
    for (int r = 0; r < 8; ++r) {
        int i  = r * 32 + lane;        // i in [0,256): f = i>>4, c16 = i&15
        int f  = i >> 4;
        int c  = (i & 15) * 4;
        float4 v = *(const float4*)(yt + f * YT_PITCH + warpk + c);
        *(float4*)(out + (g * FG_ + f) * L_ + kb + warpk + c) = v;
    }

    // ---- boundary overwrite (reference truncates; no zero-pad), full fp32 ----
    if (!interior) {
        __syncthreads();
        if (tid < FG_ * PAD1_) {
            const int f = tid / PAD1_;
            const int e = tid % PAD1_;
            const float* pk = params + (g * FG_ + f) * (J_ * W_);
            float s = 0.f;
            if (tile == 0) {
                for (int j = 0; j < J_; ++j) {
                    const float* xr = x + __ldg(rel + g * J_ + j) * L_;
                    for (int w = 0; w <= e + PAD1_; ++w)
                        s += xr[w] * pk[j * W_ + w];
                }
                out[(g * FG_ + f) * L_ + e] = s;
            } else {
                for (int j = 0; j < J_; ++j) {
                    const float* xr = x + __ldg(rel + g * J_ + j) * L_;
                    for (int w = e + 1; w < W_; ++w)
                        s += xr[L_ - W_ + w] * pk[j * W_ + w];
                }
                out[(g * FG_ + f) * L_ + (L_ - PAD1_ + e)] = s;
            }
        }
    }
}

extern "C" void kernel_launch(void* const* d_in, const int* in_sizes, int n_in,
                              void* d_out, int out_size)
{
    const float* x      = (const float*)d_in[0];
    const float* params = (const float*)d_in[1];
    const int*   rel    = (const int*)d_in[2];
    float* out = (float*)d_out;

    prep_w<<<(G_ * WS_ELEMS + 255) / 256, 256>>>(params);

    cudaFuncSetAttribute(conv_mma, cudaFuncAttributeMaxDynamicSharedMemorySize,
                         SMEM_WORDS * 4);
    dim3 grid(L_ / KTILE_, G_);   // 512 x 8
    conv_mma<<<grid, NTH_, SMEM_WORDS * 4>>>(x, params, rel, out);
}

// round 14
// speedup vs baseline: 1.1102x; 1.1102x over previous
#include <cuda_runtime.h>
#include <cstdint>

#define G_    8
#define FG_   16
#define J_    8
#define W_    31
#define PAD1_ 15
#define L_    262144
#define KTILE_ 512
#define NTH_  256

// SMEM layout (32-bit words).
// xs shifted: xs[j][s] = x[kb + s - 16], s in [0,544); consumers read +1.
#define XS_PITCH 548
#define XS_ELEMS (J_ * XS_PITCH)         // 4384
// ws4: [j][w0g][lane] -> uint4 {W[gid][w],W[gid][w+4],W[gid+8][w],W[gid+8][w+4]}
#define WS_ELEMS (J_ * 4 * 32 * 4)       // 4096 words
#define SM_XS 0
#define SM_WS (SM_XS + XS_ELEMS)         // 4384
#define SMEM_WORDS (SM_WS + WS_ELEMS)    // 8480 words = 33920 B

__device__ __forceinline__ uint32_t cvt_tf32(float f) {
    uint32_t r;
    asm("cvt.rna.tf32.f32 %0, %1;" : "=r"(r) : "f"(f));
    return r;
}

// 16B async copy, L1-bypass (.cg): global -> shared, no RF round trip.
__device__ __forceinline__ void cp16(uint32_t dst_smem, const void* src) {
    asm volatile("cp.async.cg.shared.global [%0], [%1], 16;"
                 :: "r"(dst_smem), "l"(src) : "memory");
}

__device__ __forceinline__ void mma_tf32(float d[4],
                                         uint32_t a0, uint32_t a1,
                                         uint32_t a2, uint32_t a3,
                                         uint32_t b0, uint32_t b1) {
    asm volatile(
        "mma.sync.aligned.m16n8k8.row.col.f32.tf32.tf32.f32 "
        "{%0,%1,%2,%3}, {%4,%5,%6,%7}, {%8,%9}, {%0,%1,%2,%3};"
        : "+f"(d[0]), "+f"(d[1]), "+f"(d[2]), "+f"(d[3])
        : "r"(a0), "r"(a1), "r"(a2), "r"(a3), "r"(b0), "r"(b1));
}

// CTA: one group g, 512 consecutive k, 16 filters. Warp: 64 k x 16 f.
// A[m,kk] = xs[j][m + w0 + kk] (Toeplitz alias; X[22] register window).
// x staged RAW via cp.async (tf32 = HW truncation of fp32 operand bits);
// weights staged with cvt.rna. B: one coalesced LDS.128 per (j,w0g),
// double-buffered across w0g. Epilogue: direct STG.32 — the fragment
// layout is already perfectly coalesced (4x32B full sectors per instr).
__global__ void __launch_bounds__(NTH_, 4)
conv_mma(const float* __restrict__ x,
         const float* __restrict__ params,
         const int* __restrict__ rel,
         float* __restrict__ out)
{
    extern __shared__ uint32_t sm[];
    const uint32_t smb = (uint32_t)__cvta_generic_to_shared(sm);
    const int tid  = threadIdx.x;
    const int wid  = tid >> 5;
    const int lane = tid & 31;
    const int gid  = lane >> 2;
    const int tig  = lane & 3;
    const int g    = blockIdx.y;
    const int tile = blockIdx.x;
    const int kb   = tile * KTILE_;
    const int last = L_ / KTILE_ - 1;
    const bool interior = (tile != 0) && (tile != last);

    int rows[J_];
#pragma unroll
    for (int j = 0; j < J_; ++j) rows[j] = __ldg(rel + g * J_ + j);

    // ---- stage x windows: xs[j][s] = bits(x[kb + s - 16]) ----
    if (interior) {
#pragma unroll 1
        for (int j = 0; j < J_; ++j) {
            const char* xp = (const char*)(x + rows[j] * L_ + kb - 16);
            uint32_t xd = smb + (SM_XS + j * XS_PITCH) * 4;
            for (int q = tid; q < 136; q += NTH_)
                cp16(xd + 16 * q, xp + 16 * q);
        }
        asm volatile("cp.async.commit_group;" ::: "memory");
    } else {
        // edge tiles: clamped scalar path (pollutes only overwritten outputs)
#pragma unroll 1
        for (int j = 0; j < J_; ++j) {
            const float* xr = x + rows[j] * L_;
            for (int s = tid; s < 544; s += NTH_) {
                int gi = kb + s - 16;
                gi = max(0, min(L_ - 1, gi));
                sm[SM_XS + j * XS_PITCH + s] = __float_as_uint(__ldg(xr + gi));
            }
        }
    }
    // ---- stage weights as uint4 slots, lane-ordered (rna-rounded) ----
    for (int e = tid; e < J_ * 4 * 32; e += NTH_) {
        int ln  = e & 31;
        int w0g = (e >> 5) & 3;
        int j   = e >> 7;
        int w   = w0g * 8 + (ln & 3);
        int flo = ln >> 2;
        const float* pw = params + ((g * FG_ + flo) * J_ + j) * W_;
        bool hasw4 = (w + 4 < W_);
        uint4 o;
        o.x = cvt_tf32(__ldg(pw + w));
        o.y = hasw4 ? cvt_tf32(__ldg(pw + w + 4)) : 0u;
        o.z = cvt_tf32(__ldg(pw + 8 * (J_ * W_) + w));
        o.w = hasw4 ? cvt_tf32(__ldg(pw + 8 * (J_ * W_) + w + 4)) : 0u;
        *(uint4*)(sm + SM_WS + e * 4) = o;
    }
    if (interior)
        asm volatile("cp.async.wait_group 0;" ::: "memory");
    __syncthreads();

    const int warpk = wid * 64;

    float acc[4][2][4];
#pragma unroll
    for (int mi = 0; mi < 4; ++mi)
#pragma unroll
        for (int nh = 0; nh < 2; ++nh)
#pragma unroll
            for (int q = 0; q < 4; ++q) acc[mi][nh][q] = 0.f;

#pragma unroll 1
    for (int j = 0; j < J_; ++j) {
        const uint32_t* xj = sm + SM_XS + j * XS_PITCH + 1 + warpk + gid + tig;
        const uint4* wj = (const uint4*)(sm + SM_WS + j * 512) + lane;

        // register window: X[i] = xj[4i] covers all fragments of this j
        uint32_t X[22];
#pragma unroll
        for (int i = 0; i < 22; ++i) X[i] = xj[4 * i];

        uint4 B = wj[0];
#pragma unroll
        for (int w0g = 0; w0g < 4; ++w0g) {
            uint4 Bn = wj[(w0g < 3 ? w0g + 1 : 3) * 32];   // prefetch next
#pragma unroll
            for (int mi = 0; mi < 4; ++mi) {
                const int i0 = 4 * mi + 2 * w0g;
                mma_tf32(acc[mi][0], X[i0], X[i0 + 2], X[i0 + 1], X[i0 + 3], B.x, B.y);
                mma_tf32(acc[mi][1], X[i0], X[i0 + 2], X[i0 + 1], X[i0 + 3], B.z, B.w);
            }
            B = Bn;
        }
    }

    // ---- direct fragment store: perfectly coalesced STG.32 ----
    // (f, k) per value: f = nh*8 + 2*tig + (q&1), k = warpk + 16*mi + gid + 8*(q>>1)
    {
        float* ob = out + g * FG_ * L_ + kb + warpk;
#pragma unroll
        for (int mi = 0; mi < 4; ++mi) {
#pragma unroll
            for (int nh = 0; nh < 2; ++nh) {
                const int f0 = nh * 8 + 2 * tig;
                float* o0 = ob + f0 * L_ + 16 * mi + gid;
                o0[0]          = acc[mi][nh][0];
                o0[L_]         = acc[mi][nh][1];
                o0[8]          = acc[mi][nh][2];
                o0[L_ + 8]     = acc[mi][nh][3];
            }
        }
    }

    // ---- boundary overwrite (reference truncates; no zero-pad), full fp32 ----
    if (!interior) {
        __syncthreads();   // order after the direct stores above
        if (tid < FG_ * PAD1_) {
            const int f = tid / PAD1_;
            const int e = tid % PAD1_;
            const float* pk = params + (g * FG_ + f) * (J_ * W_);
            float s = 0.f;
            if (tile == 0) {
                for (int j = 0; j < J_; ++j) {
                    const float* xr = x + __ldg(rel + g * J_ + j) * L_;
                    for (int w = 0; w <= e + PAD1_; ++w)
                        s += xr[w] * pk[j * W_ + w];
                }
                out[(g * FG_ + f) * L_ + e] = s;
            } else {
                for (int j = 0; j < J_; ++j) {
                    const float* xr = x + __ldg(rel + g * J_ + j) * L_;
                    for (int w = e + 1; w < W_; ++w)
                        s += xr[L_ - W_ + w] * pk[j * W_ + w];
                }
                out[(g * FG_ + f) * L_ + (L_ - PAD1_ + e)] = s;
            }
        }
    }
}

extern "C" void kernel_launch(void* const* d_in, const int* in_sizes, int n_in,
                              void* d_out, int out_size)
{
    const float* x      = (const float*)d_in[0];
    const float* params = (const float*)d_in[1];
    const int*   rel    = (const int*)d_in[2];
    float* out = (float*)d_out;

    cudaFuncSetAttribute(conv_mma, cudaFuncAttributeMaxDynamicSharedMemorySize,
                         SMEM_WORDS * 4);
    dim3 grid(L_ / KTILE_, G_);   // 512 x 8
    conv_mma<<<grid, NTH_, SMEM_WORDS * 4>>>(x, params, rel, out);
}

// round 15
// speedup vs baseline: 1.1377x; 1.0247x over previous
#include <cuda_runtime.h>
#include <cstdint>

#define G_    8
#define FG_   16
#define J_    8
#define W_    31
#define PAD1_ 15
#define L_    262144
#define KTILE_ 512
#define NTH_  256

// SMEM layout (32-bit words).
// xs shifted: xs[j][s] = x[kb + s - 16], s in [0,544); consumers read +1.
#define XS_PITCH 548
#define XS_ELEMS (J_ * XS_PITCH)         // 4384
// ws4: [j][w0g][lane] -> uint4 {W[gid][w],W[gid][w+4],W[gid+8][w],W[gid+8][w+4]}
#define WS_ELEMS (J_ * 4 * 32 * 4)       // 4096 words
#define SM_XS 0
#define SM_WS (SM_XS + XS_ELEMS)         // 4384
#define SMEM_WORDS (SM_WS + WS_ELEMS)    // 8480 words = 33920 B

// Pre-transformed weights: [g][slot] uint4 image, 32768 words = 128 KB (L2-hot).
__device__ uint32_t d_wt[G_ * WS_ELEMS];

__device__ __forceinline__ uint32_t cvt_tf32(float f) {
    uint32_t r;
    asm("cvt.rna.tf32.f32 %0, %1;" : "=r"(r) : "f"(f));
    return r;
}

// 16B async copy, L1-bypass (.cg): global -> shared, no RF round trip.
__device__ __forceinline__ void cp16(uint32_t dst_smem, const void* src) {
    asm volatile("cp.async.cg.shared.global [%0], [%1], 16;"
                 :: "r"(dst_smem), "l"(src) : "memory");
}

__device__ __forceinline__ void mma_tf32(float d[4],
                                         uint32_t a0, uint32_t a1,
                                         uint32_t a2, uint32_t a3,
                                         uint32_t b0, uint32_t b1) {
    asm volatile(
        "mma.sync.aligned.m16n8k8.row.col.f32.tf32.tf32.f32 "
        "{%0,%1,%2,%3}, {%4,%5,%6,%7}, {%8,%9}, {%0,%1,%2,%3};"
        : "+f"(d[0]), "+f"(d[1]), "+f"(d[2]), "+f"(d[3])
        : "r"(a0), "r"(a1), "r"(a2), "r"(a3), "r"(b0), "r"(b1));
}

// Prep: transform params [g][f][j][w] -> d_wt uint4-slot image (rna tf32).
// word idx: c = idx&3, ln = (idx>>2)&31, w0g = (idx>>7)&3, j = (idx>>9)&7, g = idx>>12
// f = (c>>1)*8 + (ln>>2), w = w0g*8 + (ln&3) + (c&1)*4 (zero-pad w>=31).
__global__ void prep_w(const float* __restrict__ params) {
    int idx = blockIdx.x * blockDim.x + threadIdx.x;
    if (idx >= G_ * WS_ELEMS) return;
    int c    = idx & 3;
    int ln   = (idx >> 2) & 31;
    int w0g  = (idx >> 7) & 3;
    int j    = (idx >> 9) & 7;
    int g    = idx >> 12;
    int f    = ((c >> 1) << 3) + (ln >> 2);
    int w    = w0g * 8 + (ln & 3) + ((c & 1) << 2);
    float v  = (w < W_) ? params[((g * FG_ + f) * J_ + j) * W_ + w] : 0.f;
    d_wt[idx] = cvt_tf32(v);
}

// CTA: one group g, 512 consecutive k, 16 filters. Warp: 64 k x 16 f.
// A[m,kk] = xs[j][m + w0 + kk] (Toeplitz alias; X[22] register window).
// x raw-bit tf32 (HW truncation); weights from prep image. ALL staging via
// cp.async in ONE group, one wait, two CTA barriers total (R14 structure).
__global__ void __launch_bounds__(NTH_, 4)
conv_mma(const float* __restrict__ x,
         const float* __restrict__ params,
         const int* __restrict__ rel,
         float* __restrict__ out)
{
    extern __shared__ uint32_t sm[];
    const uint32_t smb = (uint32_t)__cvta_generic_to_shared(sm);
    const int tid  = threadIdx.x;
    const int wid  = tid >> 5;
    const int lane = tid & 31;
    const int gid  = lane >> 2;
    const int tig  = lane & 3;
    const int g    = blockIdx.y;
    const int tile = blockIdx.x;
    const int kb   = tile * KTILE_;
    const int last = L_ / KTILE_ - 1;
    const bool interior = (tile != 0) && (tile != last);

    int rows[J_];
#pragma unroll
    for (int j = 0; j < J_; ++j) rows[j] = __ldg(rel + g * J_ + j);

    // ---- stage weights: straight 16 KB cp.async copy from prep image ----
    {
        const uint32_t* src = d_wt + g * WS_ELEMS;
        for (int e = tid; e < WS_ELEMS / 4; e += NTH_)
            cp16(smb + (SM_WS + e * 4) * 4, src + e * 4);
    }

    // ---- stage x windows: xs[j][s] = bits(x[kb + s - 16]) ----
    if (interior) {
#pragma unroll 1
        for (int j = 0; j < J_; ++j) {
            const char* xp = (const char*)(x + rows[j] * L_ + kb - 16);
            uint32_t xd = smb + (SM_XS + j * XS_PITCH) * 4;
            for (int q = tid; q < 136; q += NTH_)
                cp16(xd + 16 * q, xp + 16 * q);
        }
    } else {
        // edge tiles: clamped scalar path (pollutes only overwritten outputs)
#pragma unroll 1
        for (int j = 0; j < J_; ++j) {
            const float* xr = x + rows[j] * L_;
            for (int s = tid; s < 544; s += NTH_) {
                int gi = kb + s - 16;
                gi = max(0, min(L_ - 1, gi));
                sm[SM_XS + j * XS_PITCH + s] = __float_as_uint(__ldg(xr + gi));
            }
        }
    }
    asm volatile("cp.async.commit_group;" ::: "memory");
    asm volatile("cp.async.wait_group 0;" ::: "memory");
    __syncthreads();

    const int warpk = wid * 64;

    float acc[4][2][4];
#pragma unroll
    for (int mi = 0; mi < 4; ++mi)
#pragma unroll
        for (int nh = 0; nh < 2; ++nh)
#pragma unroll
            for (int q = 0; q < 4; ++q) acc[mi][nh][q] = 0.f;

#pragma unroll 1
    for (int j = 0; j < J_; ++j) {
        const uint32_t* xj = sm + SM_XS + j * XS_PITCH + 1 + warpk + gid + tig;
        const uint4* wj = (const uint4*)(sm + SM_WS + j * 512) + lane;

        // register window: X[i] = xj[4i] covers all fragments of this j
        uint32_t X[22];
#pragma unroll
        for (int i = 0; i < 22; ++i) X[i] = xj[4 * i];

        uint4 B = wj[0];
#pragma unroll
        for (int w0g = 0; w0g < 4; ++w0g) {
            uint4 Bn = wj[(w0g < 3 ? w0g + 1 : 3) * 32];   // prefetch next
#pragma unroll
            for (int mi = 0; mi < 4; ++mi) {
                const int i0 = 4 * mi + 2 * w0g;
                mma_tf32(acc[mi][0], X[i0], X[i0 + 2], X[i0 + 1], X[i0 + 3], B.x, B.y);
                mma_tf32(acc[mi][1], X[i0], X[i0 + 2], X[i0 + 1], X[i0 + 3], B.z, B.w);
            }
            B = Bn;
        }
    }

    // ---- direct fragment store: perfectly coalesced STG.32 ----
    // (f, k): f = nh*8 + 2*tig + (q&1), k = warpk + 16*mi + gid + 8*(q>>1)
    {
        float* ob = out + g * FG_ * L_ + kb + warpk;
#pragma unroll
        for (int mi = 0; mi < 4; ++mi) {
#pragma unroll
            for (int nh = 0; nh < 2; ++nh) {
                const int f0 = nh * 8 + 2 * tig;
                float* o0 = ob + f0 * L_ + 16 * mi + gid;
                o0[0]      = acc[mi][nh][0];
                o0[L_]     = acc[mi][nh][1];
                o0[8]      = acc[mi][nh][2];
                o0[L_ + 8] = acc[mi][nh][3];
            }
        }
    }

    // ---- boundary overwrite (reference truncates; no zero-pad), full fp32 ----
    if (!interior) {
        __syncthreads();   // order after the direct stores above
        if (tid < FG_ * PAD1_) {
            const int f = tid / PAD1_;
            const int e = tid % PAD1_;
            const float* pk = params + (g * FG_ + f) * (J_ * W_);
            float s = 0.f;
            if (tile == 0) {
                for (int j = 0; j < J_; ++j) {
                    const float* xr = x + __ldg(rel + g * J_ + j) * L_;
                    for (int w = 0; w <= e + PAD1_; ++w)
                        s += xr[w] * pk[j * W_ + w];
                }
                out[(g * FG_ + f) * L_ + e] = s;
            } else {
                for (int j = 0; j < J_; ++j) {
                    const float* xr = x + __ldg(rel + g * J_ + j) * L_;
                    for (int w = e + 1; w < W_; ++w)
                        s += xr[L_ - W_ + w] * pk[j * W_ + w];
                }
                out[(g * FG_ + f) * L_ + (L_ - PAD1_ + e)] = s;
            }
        }
    }
}

extern "C" void kernel_launch(void* const* d_in, const int* in_sizes, int n_in,
                              void* d_out, int out_size)
{
    const float* x      = (const float*)d_in[0];
    const float* params = (const float*)d_in[1];
    const int*   rel    = (const int*)d_in[2];
    float* out = (float*)d_out;

    prep_w<<<(G_ * WS_ELEMS + 255) / 256, 256>>>(params);

    cudaFuncSetAttribute(conv_mma, cudaFuncAttributeMaxDynamicSharedMemorySize,
                         SMEM_WORDS * 4);
    dim3 grid(L_ / KTILE_, G_);   // 512 x 8
    conv_mma<<<grid, NTH_, SMEM_WORDS * 4>>>(x, params, rel, out);
}

// round 16
// speedup vs baseline: 1.2447x; 1.0941x over previous
#include <cuda_runtime.h>
#include <cstdint>

#define G_    8
#define FG_   16
#define J_    8
#define W_    31
#define PAD1_ 15
#define L_    262144
#define KTILE_ 512
#define NTH_  256

// SMEM (32-bit words). Per j: copy0[272] fp16x2 pairs (2w,2w+1),
// copy1[272] pairs (2w+1,2w+2); copy1 at +272 words = +16 banks.
#define XS_PITCH 548
#define XS_ELEMS (J_ * XS_PITCH)          // 4384
// ws: [j][w0g][lane] uint4 = {b0_nh0, b1_nh0, b0_nh1, b1_nh1} fp16x2 each
#define WS_ELEMS (J_ * 2 * 32 * 4)        // 2048 words
#define SM_XS 0
#define SM_WS (SM_XS + XS_ELEMS)          // 4384
#define SMEM_WORDS (SM_WS + WS_ELEMS)     // 6432 words = 25728 B

// Pre-transformed fp16 weight image: [g][j][w0g][lane] uint4, 64 KB.
__device__ uint32_t d_wt[G_ * WS_ELEMS];

__device__ __forceinline__ uint32_t pack_h2(float lo, float hi) {
    uint32_t r;
    asm("cvt.rn.f16x2.f32 %0, %1, %2;" : "=r"(r) : "f"(hi), "f"(lo));
    return r;
}
__device__ __forceinline__ void cp16(uint32_t dst_smem, const void* src) {
    asm volatile("cp.async.cg.shared.global [%0], [%1], 16;"
                 :: "r"(dst_smem), "l"(src) : "memory");
}

__device__ __forceinline__ void mma_f16(float d[4],
                                        uint32_t a0, uint32_t a1,
                                        uint32_t a2, uint32_t a3,
                                        uint32_t b0, uint32_t b1) {
    asm volatile(
        "mma.sync.aligned.m16n8k16.row.col.f32.f16.f16.f32 "
        "{%0,%1,%2,%3}, {%4,%5,%6,%7}, {%8,%9}, {%0,%1,%2,%3};"
        : "+f"(d[0]), "+f"(d[1]), "+f"(d[2]), "+f"(d[3])
        : "r"(a0), "r"(a1), "r"(a2), "r"(a3), "r"(b0), "r"(b1));
}

// Prep: params [g][f][j][w] -> fp16 B-fragment image.
// uint4 idx: lane = idx&31, w0g = (idx>>5)&1, j = (idx>>6)&7, g = idx>>9.
__global__ void prep_w(const float* __restrict__ params) {
    int idx = blockIdx.x * blockDim.x + threadIdx.x;
    if (idx >= G_ * J_ * 2 * 32) return;
    int lane = idx & 31;
    int w0g  = (idx >> 5) & 1;
    int j    = (idx >> 6) & 7;
    int g    = idx >> 9;
    int gidl = lane >> 2;
    int w    = 16 * w0g + 2 * (lane & 3);
    auto Wv = [&](int f, int ww) -> float {
        return (ww < W_) ? params[((g * FG_ + f) * J_ + j) * W_ + ww] : 0.f;
    };
    uint4 o;
    o.x = pack_h2(Wv(gidl, w),         Wv(gidl, w + 1));
    o.y = pack_h2(Wv(gidl, w + 8),     Wv(gidl, w + 9));
    o.z = pack_h2(Wv(gidl + 8, w),     Wv(gidl + 8, w + 1));
    o.w = pack_h2(Wv(gidl + 8, w + 8), Wv(gidl + 8, w + 9));
    *(uint4*)(d_wt + idx * 4) = o;
}

// CTA: group g, 512 consecutive k, 16 filters. Warp: 64 k x 16 f.
// fp16 m16n8k16, K split in 2 w-chunks of 16. Toeplitz: A[r][kk] =
// win[warpk+16mi+16w0g+1 + r + kk]; a1 == a2; X[11] fp16x2 window per j.
__global__ void __launch_bounds__(NTH_, 4)
conv_mma(const float* __restrict__ x,
         const float* __restrict__ params,
         const int* __restrict__ rel,
         float* __restrict__ out)
{
    extern __shared__ uint32_t sm[];
    const uint32_t smb = (uint32_t)__cvta_generic_to_shared(sm);
    const int tid  = threadIdx.x;
    const int wid  = tid >> 5;
    const int lane = tid & 31;
    const int gid  = lane >> 2;
    const int tig  = lane & 3;
    const int g    = blockIdx.y;
    const int tile = blockIdx.x;
    const int kb   = tile * KTILE_;
    const int last = L_ / KTILE_ - 1;
    const bool interior = (tile != 0) && (tile != last);

    int rows[J_];
#pragma unroll
    for (int j = 0; j < J_; ++j) rows[j] = __ldg(rel + g * J_ + j);

    // ---- weights: 8 KB cp.async from prep image ----
    {
        const uint32_t* src = d_wt + g * WS_ELEMS;
#pragma unroll
        for (int e = tid; e < WS_ELEMS / 4; e += NTH_)
            cp16(smb + (SM_WS + e * 4) * 4, src + e * 4);
        asm volatile("cp.async.commit_group;" ::: "memory");
    }

    // ---- x windows: win[s] = x[kb + s - 16], s in [0,544) as fp16 pairs ----
    if (interior) {
#pragma unroll 1
        for (int j = 0; j < J_; ++j) {
            const float*  xe  = x + rows[j] * L_ + kb - 16;
            const float4* xp4 = (const float4*)xe;
            uint32_t* row = sm + SM_XS + j * XS_PITCH;
            for (int q = tid; q < 136; q += NTH_) {
                float4 v = __ldg(xp4 + q);
                float x4 = __ldg(xe + 4 * q + 4);
                uint2 c0, c1;
                c0.x = pack_h2(v.x, v.y);  c0.y = pack_h2(v.z, v.w);
                c1.x = pack_h2(v.y, v.z);  c1.y = pack_h2(v.w, x4);
                *(uint2*)(row + 2 * q)       = c0;
                *(uint2*)(row + 272 + 2 * q) = c1;
            }
        }
    } else {
        // edge tiles: clamped scalar path (pollutes only overwritten outputs)
#pragma unroll 1
        for (int j = 0; j < J_; ++j) {
            const float* xr = x + rows[j] * L_;
            uint32_t* row = sm + SM_XS + j * XS_PITCH;
            for (int w = tid; w < 272; w += NTH_) {
                int s0 = kb + 2 * w - 16;
                float v0 = __ldg(xr + max(0, min(L_ - 1, s0)));
                float v1 = __ldg(xr + max(0, min(L_ - 1, s0 + 1)));
                float v2 = __ldg(xr + max(0, min(L_ - 1, s0 + 2)));
                row[w]       = pack_h2(v0, v1);
                row[272 + w] = pack_h2(v1, v2);
            }
        }
    }
    asm volatile("cp.async.wait_group 0;" ::: "memory");
    __syncthreads();

    const int warpk = wid * 64;

    float acc[4][2][4];
#pragma unroll
    for (int mi = 0; mi < 4; ++mi)
#pragma unroll
        for (int nh = 0; nh < 2; ++nh)
#pragma unroll
            for (int q = 0; q < 4; ++q) acc[mi][nh][q] = 0.f;

    // per-lane A window base: half-position h0 = warpk + 1 + gid + 2*tig
    const int h0 = warpk + 1 + gid + 2 * tig;
    const int P  = h0 & 1;
    const int wb = (h0 - P) >> 1;

#pragma unroll 1
    for (int j = 0; j < J_; ++j) {
        const uint32_t* xw = sm + SM_XS + j * XS_PITCH + P * 272 + wb;
        const uint4* wj = (const uint4*)(sm + SM_WS + j * 256) + lane;

        // X[u] = fp16 pair at half-positions (h0+8u, h0+8u+1)
        uint32_t X[11];
#pragma unroll
        for (int u = 0; u < 11; ++u) X[u] = xw[4 * u];

        uint4 B0 = wj[0];
        uint4 B1 = wj[32];
#pragma unroll
        for (int w0g = 0; w0g < 2; ++w0g) {
            const uint4 B = w0g ? B1 : B0;
#pragma unroll
            for (int mi = 0; mi < 4; ++mi) {
                const int u0 = 2 * (mi + w0g);
                // a0 = pair(t0), a1 = a2 = pair(t0+8), a3 = pair(t0+16)
                mma_f16(acc[mi][0], X[u0], X[u0 + 1], X[u0 + 1], X[u0 + 2],
                        B.x, B.y);
                mma_f16(acc[mi][1], X[u0], X[u0 + 1], X[u0 + 1], X[u0 + 2],
                        B.z, B.w);
            }
        }
    }

    // ---- direct fragment store (same D layout as m16n8k8) ----
    // d0:(k0,f0) d1:(k0,f0+1) d2:(k0+8,f0) d3:(k0+8,f0+1);
    // k0 = warpk+16mi+gid, f0 = nh*8+2tig
    {
        float* ob = out + g * FG_ * L_ + kb + warpk;
#pragma unroll
        for (int mi = 0; mi < 4; ++mi) {
#pragma unroll
            for (int nh = 0; nh < 2; ++nh) {
                const int f0 = nh * 8 + 2 * tig;
                float* o0 = ob + f0 * L_ + 16 * mi + gid;
                o0[0]      = acc[mi][nh][0];
                o0[L_]     = acc[mi][nh][1];
                o0[8]      = acc[mi][nh][2];
                o0[L_ + 8] = acc[mi][nh][3];
            }
        }
    }

    // ---- boundary overwrite (reference truncates; no zero-pad), full fp32 ----
    if (!interior) {
        __syncthreads();
        if (tid < FG_ * PAD1_) {
            const int f = tid / PAD1_;
            const int e = tid % PAD1_;
            const float* pk = params + (g * FG_ + f) * (J_ * W_);
            float s = 0.f;
            if (tile == 0) {
                for (int j = 0; j < J_; ++j) {
                    const float* xr = x + __ldg(rel + g * J_ + j) * L_;
                    for (int w = 0; w <= e + PAD1_; ++w)
                        s += xr[w] * pk[j * W_ + w];
                }
                out[(g * FG_ + f) * L_ + e] = s;
            } else {
                for (int j = 0; j < J_; ++j) {
                    const float* xr = x + __ldg(rel + g * J_ + j) * L_;
                    for (int w = e + 1; w < W_; ++w)
                        s += xr[L_ - W_ + w] * pk[j * W_ + w];
                }
                out[(g * FG_ + f) * L_ + (L_ - PAD1_ + e)] = s;
            }
        }
    }
}

extern "C" void kernel_launch(void* const* d_in, const int* in_sizes, int n_in,
                              void* d_out, int out_size)
{
    const float* x      = (const float*)d_in[0];
    const float* params = (const float*)d_in[1];
    const int*   rel    = (const int*)d_in[2];
    float* out = (float*)d_out;

    prep_w<<<(G_ * J_ * 2 * 32 + 255) / 256, 256>>>(params);

    cudaFuncSetAttribute(conv_mma, cudaFuncAttributeMaxDynamicSharedMemorySize,
                         SMEM_WORDS * 4);
    dim3 grid(L_ / KTILE_, G_);   // 512 x 8
    conv_mma<<<grid, NTH_, SMEM_WORDS * 4>>>(x, params, rel, out);
}